// round 4
// baseline (speedup 1.0000x reference)
#include <cuda_runtime.h>
#include <cuda_bf16.h>
#include <cstdint>

// Problem constants (N=8192, X=H=Y=1024)
#define NR 8192
#define XD 1024
#define KE2 2048           // [hi | lo] extended-K storage
#define CHUNKS 64
#define RPC 128

// ---------------------------------------------------------------------------
// Device scratch (allocation-free rule)
// ---------------------------------------------------------------------------
__device__ float g_Xs[(size_t)NR * XD];              // exclusive prefix-sum of x
__device__ __nv_bfloat16 g_Xse [(size_t)NR * KE2];   // ext [hi|lo] of Xs
__device__ __nv_bfloat16 g_WqTe[(size_t)XD * KE2];   // ext [hi|lo] of Wq^T
__device__ __nv_bfloat16 g_WkTe[(size_t)XD * KE2];   // ext [hi|lo] of Wk^T
__device__ float g_Mpart[3 * (size_t)XD * XD];       // per-pass partials of M
__device__ __nv_bfloat16 g_Me[(size_t)XD * KE2];     // ext [hi|lo] of M
__device__ float g_r[NR];                            // fused row-dot accumulators
__device__ float g_part[CHUNKS * XD];
__device__ float g_off [CHUNKS * XD];
__device__ float g_upart[8 * XD];
__device__ float g_wpart[8 * XD];
__device__ float g_u[XD];
__device__ float g_w[XD];
__device__ float g_c0;

// ---------------------------------------------------------------------------
// PTX helpers (base sm_80+ ISA only)
// ---------------------------------------------------------------------------
__device__ __forceinline__ uint32_t smem_u32(const void* p) {
    uint32_t a;
    asm("{ .reg .u64 t; cvta.to.shared.u64 t, %1; cvt.u32.u64 %0, t; }" : "=r"(a) : "l"(p));
    return a;
}
#define CP_ASYNC16(dst, src) \
    asm volatile("cp.async.cg.shared.global [%0], [%1], 16;" :: "r"(dst), "l"(src))
#define CP_COMMIT() asm volatile("cp.async.commit_group;" ::: "memory")
#define CP_WAIT2()  asm volatile("cp.async.wait_group 2;" ::: "memory")
#define CP_WAIT1()  asm volatile("cp.async.wait_group 1;" ::: "memory")
#define CP_WAIT0()  asm volatile("cp.async.wait_group 0;" ::: "memory")

__device__ __forceinline__ void ldsm4(uint32_t& r0, uint32_t& r1, uint32_t& r2,
                                      uint32_t& r3, uint32_t addr) {
    asm volatile("ldmatrix.sync.aligned.m8n8.x4.shared.b16 {%0,%1,%2,%3}, [%4];"
                 : "=r"(r0), "=r"(r1), "=r"(r2), "=r"(r3) : "r"(addr));
}
__device__ __forceinline__ void mma_bf16(float* c, uint32_t a0, uint32_t a1,
                                         uint32_t a2, uint32_t a3,
                                         uint32_t b0, uint32_t b1) {
    asm volatile(
        "mma.sync.aligned.m16n8k16.row.col.f32.bf16.bf16.f32 "
        "{%0,%1,%2,%3}, {%4,%5,%6,%7}, {%8,%9}, {%0,%1,%2,%3};"
        : "+f"(c[0]), "+f"(c[1]), "+f"(c[2]), "+f"(c[3])
        : "r"(a0), "r"(a1), "r"(a2), "r"(a3), "r"(b0), "r"(b1));
}
__device__ __forceinline__ uint32_t swz(uint32_t b) { return b ^ ((b >> 3) & 0x70); }

__device__ __forceinline__ void split1(float v, __nv_bfloat16& h, __nv_bfloat16& l) {
    h = __float2bfloat16_rn(v);
    l = __float2bfloat16_rn(v - __bfloat162float(h));
}

// ---------------------------------------------------------------------------
// bf16x3 GEMM (split over blockIdx.z passes):
//   C[m][n] += sum_k A[m][aoff+k] * B[n][boff+k],  k in [0,1024)
//   pass 0: (hi,hi)  pass 1: (lo,hi)  pass 2: (hi,lo)
// 128x128 tile, BK=64/stage, 4-stage cp.async, 8 warps (32m x 64n each).
// EPI=0: plain store into Mpart[pass]. EPI=1: fused row-dot atomicAdd to g_r.
// ---------------------------------------------------------------------------
#define BK 64
#define NSTG 4
#define NS 16                        // K-stages per pass (1024/64)
#define TILEB (128 * BK * 2)         // 16 KB per operand stage
#define STAGEB (2 * TILEB)
#define GSMEM (1024 + NSTG * STAGEB) // 132 KB

template <int EPI>
__global__ void __launch_bounds__(256)
gemm_ext(const __nv_bfloat16* __restrict__ A,
         const __nv_bfloat16* __restrict__ B,
         float* __restrict__ C,
         const float* __restrict__ xx) {
    extern __shared__ char smem_raw[];
    __shared__ float red[128];
    uint32_t raw = smem_u32(smem_raw);
    uint32_t ab = (raw + 1023u) & ~1023u;

    const int tid = threadIdx.x;
    const int wid = tid >> 5;
    const int lane = tid & 31;
    const int m0 = blockIdx.y * 128;
    const int n0 = blockIdx.x * 128;
    const int pass = blockIdx.z;
    const int aoff = (pass == 1) ? XD : 0;
    const int boff = (pass == 2) ? XD : 0;
    const int wm = (wid & 3) * 32;
    const int wn = (wid >> 2) * 64;

    const __nv_bfloat16* gA = A + (size_t)m0 * KE2 + aoff;
    const __nv_bfloat16* gB = B + (size_t)n0 * KE2 + boff;

    float acc[2][8][4];
    #pragma unroll
    for (int i = 0; i < 2; i++)
        #pragma unroll
        for (int j = 0; j < 8; j++)
            #pragma unroll
            for (int q = 0; q < 4; q++) acc[i][j][q] = 0.f;

    const int lrow = tid >> 3;        // load row 0..127 (2 rows per 16B unit pass)
    const int lc16 = tid & 7;         // 16B chunk in 128B row
    auto issue = [&](int s) {
        const uint32_t sa = ab + (s & (NSTG - 1)) * STAGEB;
        const uint32_t sb = sa + TILEB;
        const int kb = s * BK;
        #pragma unroll
        for (int i = 0; i < 4; i++) {
            int row = lrow + i * 32;
            uint32_t so = swz((uint32_t)(row * 128 + lc16 * 16));
            CP_ASYNC16(sa + so, gA + (size_t)row * KE2 + kb + lc16 * 8);
            CP_ASYNC16(sb + so, gB + (size_t)row * KE2 + kb + lc16 * 8);
        }
        CP_COMMIT();
    };
    issue(0); issue(1); issue(2);

    const int lr = lane & 15;
    const int lc = lane >> 4;

    for (int s = 0; s < NS; s++) {
        if (s <= NS - 3)      { CP_WAIT2(); }
        else if (s == NS - 2) { CP_WAIT1(); }
        else                  { CP_WAIT0(); }
        __syncthreads();
        if (s + 3 < NS) issue(s + 3);

        const uint32_t sa = ab + (s & (NSTG - 1)) * STAGEB;
        const uint32_t sb = sa + TILEB;
        #pragma unroll
        for (int s4 = 0; s4 < 4; s4++) {
            const int xcol = s4 * 32 + lc * 16;
            uint32_t a[2][4];
            #pragma unroll
            for (int mm = 0; mm < 2; mm++) {
                int row = wm + mm * 16 + lr;
                uint32_t addr = sa + row * 128 + (xcol ^ ((row & 7) * 16));
                ldsm4(a[mm][0], a[mm][1], a[mm][2], a[mm][3], addr);
            }
            #pragma unroll
            for (int nb = 0; nb < 4; nb++) {
                int row = wn + nb * 16 + lr;
                uint32_t addr = sb + row * 128 + (xcol ^ ((row & 7) * 16));
                uint32_t r0, r1, r2, r3;
                ldsm4(r0, r1, r2, r3, addr);
                #pragma unroll
                for (int mm = 0; mm < 2; mm++) {
                    mma_bf16(acc[mm][2 * nb],     a[mm][0], a[mm][1], a[mm][2], a[mm][3], r0, r2);
                    mma_bf16(acc[mm][2 * nb + 1], a[mm][0], a[mm][1], a[mm][2], a[mm][3], r1, r3);
                }
            }
        }
    }

    const int qr = lane >> 2;
    const int qc = (lane & 3) * 2;

    if (EPI == 0) {
        // plain per-pass store
        float* Cp = C + (size_t)pass * XD * XD;
        #pragma unroll
        for (int mm = 0; mm < 2; mm++) {
            #pragma unroll
            for (int j = 0; j < 8; j++) {
                int r = m0 + wm + mm * 16 + qr;
                int c = n0 + wn + j * 8 + qc;
                *(float2*)&Cp[(size_t)r * XD + c]       = make_float2(acc[mm][j][0], acc[mm][j][1]);
                *(float2*)&Cp[(size_t)(r + 8) * XD + c] = make_float2(acc[mm][j][2], acc[mm][j][3]);
            }
        }
    } else {
        // fused row-dot: r[i] += sum_c x[i][c] * P_tile[i][c]
        float pr[4] = {0.f, 0.f, 0.f, 0.f};   // rows wm+qr, wm+qr+8, wm+16+qr, wm+16+qr+8
        #pragma unroll
        for (int mm = 0; mm < 2; mm++) {
            int r = m0 + wm + mm * 16 + qr;
            #pragma unroll
            for (int j = 0; j < 8; j++) {
                int c = n0 + wn + j * 8 + qc;
                float2 x0 = *(const float2*)&xx[(size_t)r * XD + c];
                float2 x1 = *(const float2*)&xx[(size_t)(r + 8) * XD + c];
                pr[mm * 2]     += acc[mm][j][0] * x0.x + acc[mm][j][1] * x0.y;
                pr[mm * 2 + 1] += acc[mm][j][2] * x1.x + acc[mm][j][3] * x1.y;
            }
        }
        #pragma unroll
        for (int q = 0; q < 4; q++) {
            pr[q] += __shfl_xor_sync(0xFFFFFFFFu, pr[q], 1);
            pr[q] += __shfl_xor_sync(0xFFFFFFFFu, pr[q], 2);
        }
        if (tid < 128) red[tid] = 0.f;
        __syncthreads();
        if ((lane & 3) == 0) {
            atomicAdd(&red[wm + qr],      pr[0]);
            atomicAdd(&red[wm + qr + 8],  pr[1]);
            atomicAdd(&red[wm + 16 + qr], pr[2]);
            atomicAdd(&red[wm + 24 + qr], pr[3]);
        }
        __syncthreads();
        if (tid < 128) atomicAdd(&C[m0 + tid], red[tid]);
    }
}

// ---------------------------------------------------------------------------
// Transpose + bf16 hi/lo split: out[a][c]=hi(in[c][a]), out[a][1024+c]=lo
// ---------------------------------------------------------------------------
__global__ void transpose_ext(const float* __restrict__ in,
                              __nv_bfloat16* __restrict__ out) {
    __shared__ float t[32][33];
    int bx = blockIdx.x * 32, by = blockIdx.y * 32;
    #pragma unroll
    for (int j = 0; j < 32; j += 8)
        t[threadIdx.y + j][threadIdx.x] = in[(size_t)(by + threadIdx.y + j) * XD + bx + threadIdx.x];
    __syncthreads();
    #pragma unroll
    for (int j = 0; j < 32; j += 8) {
        float v = t[threadIdx.x][threadIdx.y + j];
        __nv_bfloat16 h, l;
        split1(v, h, l);
        size_t r = bx + threadIdx.y + j;
        int c = by + threadIdx.x;
        out[r * KE2 + c]      = h;
        out[r * KE2 + XD + c] = l;
    }
}

// ---------------------------------------------------------------------------
// Scan: exclusive prefix sum of x rows -> g_Xs (fp32) + g_Xse (hi|lo bf16)
// ---------------------------------------------------------------------------
__global__ void colsum_kernel(const float* __restrict__ x) {
    int col = blockIdx.x * 256 + threadIdx.x;
    int ch  = blockIdx.y;
    const float* p = x + (size_t)ch * RPC * XD + col;
    float s = 0.f;
    #pragma unroll 8
    for (int r = 0; r < RPC; r++) s += p[(size_t)r * XD];
    g_part[ch * XD + col] = s;
}
__global__ void scanoff_kernel() {
    int col = blockIdx.x * 256 + threadIdx.x;
    float run = 0.f;
    #pragma unroll
    for (int c = 0; c < CHUNKS; c++) {
        g_off[c * XD + col] = run;
        run += g_part[c * XD + col];
    }
}
__global__ void writeXs_ext(const float* __restrict__ x) {
    int col = blockIdx.x * 256 + threadIdx.x;
    int ch  = blockIdx.y;
    float run = g_off[ch * XD + col];
    #pragma unroll 4
    for (int r = 0; r < RPC; r++) {
        size_t row = (size_t)ch * RPC + r;
        size_t idx = row * XD + col;
        g_Xs[idx] = run;
        __nv_bfloat16 h, l;
        split1(run, h, l);
        g_Xse[row * KE2 + col]      = h;
        g_Xse[row * KE2 + XD + col] = l;
        run += x[idx];
    }
}

// ---------------------------------------------------------------------------
// Sum the 3 M partials, split to [hi|lo] ext
// ---------------------------------------------------------------------------
__global__ void ext_sum3(__nv_bfloat16* __restrict__ out) {
    const size_t row = blockIdx.x;
    const int c = threadIdx.x * 4;
    const size_t base = row * XD + c;
    float4 a = *(const float4*)&g_Mpart[base];
    float4 b = *(const float4*)&g_Mpart[(size_t)XD * XD + base];
    float4 d = *(const float4*)&g_Mpart[2 * (size_t)XD * XD + base];
    float v[4] = {a.x + b.x + d.x, a.y + b.y + d.y, a.z + b.z + d.z, a.w + b.w + d.w};
    unsigned short hb[4], lb[4];
    #pragma unroll
    for (int i = 0; i < 4; i++) {
        __nv_bfloat16 h, l;
        split1(v[i], h, l);
        hb[i] = *reinterpret_cast<unsigned short*>(&h);
        lb[i] = *reinterpret_cast<unsigned short*>(&l);
    }
    unsigned short* ob = reinterpret_cast<unsigned short*>(out) + row * KE2;
    *(ushort4*)(ob + c)      = make_ushort4(hb[0], hb[1], hb[2], hb[3]);
    *(ushort4*)(ob + XD + c) = make_ushort4(lb[0], lb[1], lb[2], lb[3]);
}

// ---------------------------------------------------------------------------
// Small vectors: u = Wq^T bk, w = Wk^T bq, c0 = bq.bk
// ---------------------------------------------------------------------------
__global__ void smallvec_part_kernel(const float* __restrict__ Wq,
                                     const float* __restrict__ Wk,
                                     const float* __restrict__ bk,
                                     const float* __restrict__ bq) {
    int a  = blockIdx.x * 256 + threadIdx.x;
    int hb = blockIdx.y;
    float su = 0.f, sw = 0.f;
    #pragma unroll 4
    for (int h = hb * 128; h < hb * 128 + 128; h++) {
        su += Wq[(size_t)h * XD + a] * bk[h];
        sw += Wk[(size_t)h * XD + a] * bq[h];
    }
    g_upart[hb * XD + a] = su;
    g_wpart[hb * XD + a] = sw;
}
__global__ void smallvec_reduce_kernel() {
    int a = blockIdx.x * 256 + threadIdx.x;
    float su = 0.f, sw = 0.f;
    #pragma unroll
    for (int p = 0; p < 8; p++) { su += g_upart[p * XD + a]; sw += g_wpart[p * XD + a]; }
    g_u[a] = su;
    g_w[a] = sw;
}
__global__ void c0_kernel(const float* __restrict__ bq, const float* __restrict__ bk) {
    __shared__ float red[256];
    float s = 0.f;
    for (int i = threadIdx.x; i < XD; i += 256) s += bq[i] * bk[i];
    red[threadIdx.x] = s;
    __syncthreads();
    for (int st = 128; st > 0; st >>= 1) {
        if (threadIdx.x < st) red[threadIdx.x] += red[threadIdx.x + st];
        __syncthreads();
    }
    if (threadIdx.x == 0) g_c0 = red[0];
}

__global__ void zero_r_kernel() {
    g_r[blockIdx.x * 256 + threadIdx.x] = 0.f;
}

// ---------------------------------------------------------------------------
// Finalize: out[i,:] = g_r[i] + i*(u.x_i) + w.Xs_i + i*c0
// ---------------------------------------------------------------------------
__global__ void finalize_kernel(const float* __restrict__ x, float* __restrict__ out) {
    const int i = blockIdx.x;
    const float fi = (float)i;
    const int tid = threadIdx.x;
    size_t rb = (size_t)i * XD;
    float p = 0.f;
    #pragma unroll
    for (int c = tid; c < XD; c += 256)
        p += fi * x[rb + c] * g_u[c] + g_w[c] * g_Xs[rb + c];
    __shared__ float red[256];
    red[tid] = p;
    __syncthreads();
    for (int st = 128; st > 0; st >>= 1) {
        if (tid < st) red[tid] += red[tid + st];
        __syncthreads();
    }
    float r = red[0] + g_r[i] + fi * g_c0;
    float4 rv = make_float4(r, r, r, r);
    #pragma unroll
    for (int c = tid * 4; c < XD; c += 256 * 4)
        *(float4*)&out[rb + c] = rv;
}

// ---------------------------------------------------------------------------
// kernel_launch — inputs: x, Wk, bk, Wv, bv, Wq, bq  (Wv/bv unused: V:=ones)
// ---------------------------------------------------------------------------
extern "C" void kernel_launch(void* const* d_in, const int* in_sizes, int n_in,
                              void* d_out, int out_size) {
    const float* x  = (const float*)d_in[0];
    const float* Wk = (const float*)d_in[1];
    const float* bk = (const float*)d_in[2];
    const float* Wq = (const float*)d_in[5];
    const float* bq = (const float*)d_in[6];
    float* out = (float*)d_out;

    __nv_bfloat16 *Xse, *Me, *WqTe, *WkTe;
    float *Mpart, *r;
    cudaGetSymbolAddress((void**)&Xse,   g_Xse);
    cudaGetSymbolAddress((void**)&Me,    g_Me);
    cudaGetSymbolAddress((void**)&WqTe,  g_WqTe);
    cudaGetSymbolAddress((void**)&WkTe,  g_WkTe);
    cudaGetSymbolAddress((void**)&Mpart, g_Mpart);
    cudaGetSymbolAddress((void**)&r,     g_r);

    cudaFuncSetAttribute(gemm_ext<0>, cudaFuncAttributeMaxDynamicSharedMemorySize, GSMEM);
    cudaFuncSetAttribute(gemm_ext<1>, cudaFuncAttributeMaxDynamicSharedMemorySize, GSMEM);

    // 1) transpose + split weights
    transpose_ext<<<dim3(32, 32), dim3(32, 8)>>>(Wq, WqTe);
    transpose_ext<<<dim3(32, 32), dim3(32, 8)>>>(Wk, WkTe);

    // 2) prefix sum of x -> Xs fp32 + Xse ext
    colsum_kernel<<<dim3(XD / 256, CHUNKS), 256>>>(x);
    scanoff_kernel<<<XD / 256, 256>>>();
    writeXs_ext<<<dim3(XD / 256, CHUNKS), 256>>>(x);

    // 3) M = Wq^T Wk (3 split passes -> partials), then sum+split to ext
    gemm_ext<0><<<dim3(XD / 128, XD / 128, 3), 256, GSMEM>>>(WqTe, WkTe, Mpart, nullptr);
    ext_sum3<<<XD, 256>>>(Me);

    // 4) u, w, c0
    smallvec_part_kernel<<<dim3(XD / 256, 8), 256>>>(Wq, Wk, bk, bq);
    smallvec_reduce_kernel<<<XD / 256, 256>>>();
    c0_kernel<<<1, 256>>>(bq, bk);

    // 5) fused P-GEMM + row-dot: g_r[i] = sum_a x[i][a] * (Xs M^T)[i][a]
    zero_r_kernel<<<NR / 256, 256>>>();
    gemm_ext<1><<<dim3(XD / 128, NR / 128, 3), 256, GSMEM>>>(Xse, Me, r, x);

    // 6) broadcast + affine terms
    finalize_kernel<<<NR, 256>>>(x, out);
}

// round 5
// speedup vs baseline: 1.1167x; 1.1167x over previous
#include <cuda_runtime.h>
#include <cuda_bf16.h>
#include <cstdint>

// Problem constants (N=8192, X=H=Y=1024)
#define NR 8192
#define XD 1024
#define KE2 2048           // [hi | lo] extended-K storage
#define CHUNKS 64
#define RPC 128

// ---------------------------------------------------------------------------
// Device scratch (allocation-free rule)
// ---------------------------------------------------------------------------
__device__ __nv_bfloat16 g_Xse [(size_t)NR * KE2];   // ext [hi|lo] of Xs
__device__ __nv_bfloat16 g_WqTe[(size_t)XD * KE2];   // ext [hi|lo] of Wq^T
__device__ __nv_bfloat16 g_WkTe[(size_t)XD * KE2];   // ext [hi|lo] of Wk^T
__device__ float g_Mpart[3 * (size_t)XD * XD];       // per-pass partials of M
__device__ __nv_bfloat16 g_Me[(size_t)XD * KE2];     // ext [hi|lo] of M
__device__ float g_r[NR];                            // fused row-dot accumulators
__device__ float g_e[NR];                            // e_i = u . x_i
__device__ float g_d[NR];                            // d_i = w . x_i
__device__ float g_s[NR];                            // s_i = sum_{j<i} d_j
__device__ float g_part[CHUNKS * XD];
__device__ float g_upart[8 * XD];
__device__ float g_wpart[8 * XD];
__device__ float g_u[XD];
__device__ float g_w[XD];
__device__ float g_c0;

// ---------------------------------------------------------------------------
// PTX helpers (base sm_80+ ISA only)
// ---------------------------------------------------------------------------
__device__ __forceinline__ uint32_t smem_u32(const void* p) {
    uint32_t a;
    asm("{ .reg .u64 t; cvta.to.shared.u64 t, %1; cvt.u32.u64 %0, t; }" : "=r"(a) : "l"(p));
    return a;
}
#define CP_ASYNC16(dst, src) \
    asm volatile("cp.async.cg.shared.global [%0], [%1], 16;" :: "r"(dst), "l"(src))
#define CP_COMMIT() asm volatile("cp.async.commit_group;" ::: "memory")
#define CP_WAIT1()  asm volatile("cp.async.wait_group 1;" ::: "memory")
#define CP_WAIT0()  asm volatile("cp.async.wait_group 0;" ::: "memory")

__device__ __forceinline__ void ldsm4(uint32_t& r0, uint32_t& r1, uint32_t& r2,
                                      uint32_t& r3, uint32_t addr) {
    asm volatile("ldmatrix.sync.aligned.m8n8.x4.shared.b16 {%0,%1,%2,%3}, [%4];"
                 : "=r"(r0), "=r"(r1), "=r"(r2), "=r"(r3) : "r"(addr));
}
__device__ __forceinline__ void mma_bf16(float* c, uint32_t a0, uint32_t a1,
                                         uint32_t a2, uint32_t a3,
                                         uint32_t b0, uint32_t b1) {
    asm volatile(
        "mma.sync.aligned.m16n8k16.row.col.f32.bf16.bf16.f32 "
        "{%0,%1,%2,%3}, {%4,%5,%6,%7}, {%8,%9}, {%0,%1,%2,%3};"
        : "+f"(c[0]), "+f"(c[1]), "+f"(c[2]), "+f"(c[3])
        : "r"(a0), "r"(a1), "r"(a2), "r"(a3), "r"(b0), "r"(b1));
}
__device__ __forceinline__ uint32_t swz(uint32_t b) { return b ^ ((b >> 3) & 0x70); }

__device__ __forceinline__ void split1(float v, __nv_bfloat16& h, __nv_bfloat16& l) {
    h = __float2bfloat16_rn(v);
    l = __float2bfloat16_rn(v - __bfloat162float(h));
}

// ---------------------------------------------------------------------------
// bf16x3 GEMM, split over blockIdx.z passes:
//   pass 0: (hi,hi)  pass 1: (lo,hi)  pass 2: (hi,lo)
// Block tile 256x128, 8 warps of 64x64 (4m x 2n), BK=64, 3-stage cp.async,
// ONE __syncthreads per stage.
// EPI=0: plain store into Mpart[pass]. EPI=1: fused row-dot atomicAdd to g_r.
// ---------------------------------------------------------------------------
#define BK 64
#define NS 16                         // K-stages per pass (1024/64)
#define ABYTES (256 * BK * 2)         // 32 KB A stage
#define BBYTES (128 * BK * 2)         // 16 KB B stage
#define STAGEB (ABYTES + BBYTES)      // 48 KB
#define GSMEM (1024 + 3 * STAGEB)     // ~145 KB

template <int EPI>
__global__ void __launch_bounds__(256, 1)
gemm_ext(const __nv_bfloat16* __restrict__ A,
         const __nv_bfloat16* __restrict__ B,
         float* __restrict__ C,
         const float* __restrict__ xx) {
    extern __shared__ char smem_raw[];
    __shared__ float red[256];
    uint32_t raw = smem_u32(smem_raw);
    uint32_t ab = (raw + 1023u) & ~1023u;

    const int tid = threadIdx.x;
    const int wid = tid >> 5;
    const int lane = tid & 31;
    const int m0 = blockIdx.y * 256;
    const int n0 = blockIdx.x * 128;
    const int pass = blockIdx.z;
    const int aoff = (pass == 1) ? XD : 0;
    const int boff = (pass == 2) ? XD : 0;
    const int wm = (wid & 3) * 64;    // warp row offset (0,64,128,192)
    const int wn = (wid >> 2) * 64;   // warp col offset (0,64)

    const __nv_bfloat16* gA = A + (size_t)m0 * KE2 + aoff;
    const __nv_bfloat16* gB = B + (size_t)n0 * KE2 + boff;

    float acc[4][8][4];
    #pragma unroll
    for (int i = 0; i < 4; i++)
        #pragma unroll
        for (int j = 0; j < 8; j++)
            #pragma unroll
            for (int q = 0; q < 4; q++) acc[i][j][q] = 0.f;

    const int lrow = tid >> 3;
    const int lc16 = tid & 7;
    auto issue = [&](int s, int buf) {
        const uint32_t sa = ab + buf * STAGEB;
        const uint32_t sb = sa + ABYTES;
        const int kb = s * BK;
        #pragma unroll
        for (int i = 0; i < 8; i++) {
            int row = lrow + i * 32;
            uint32_t so = swz((uint32_t)(row * 128 + lc16 * 16));
            CP_ASYNC16(sa + so, gA + (size_t)row * KE2 + kb + lc16 * 8);
        }
        #pragma unroll
        for (int i = 0; i < 4; i++) {
            int row = lrow + i * 32;
            uint32_t so = swz((uint32_t)(row * 128 + lc16 * 16));
            CP_ASYNC16(sb + so, gB + (size_t)row * KE2 + kb + lc16 * 8);
        }
        CP_COMMIT();
    };
    issue(0, 0);
    issue(1, 1);

    const int lr = lane & 15;
    const int lc = lane >> 4;

    int buf = 0;
    for (int s = 0; s < NS; s++) {
        if (s + 1 < NS) { CP_WAIT1(); } else { CP_WAIT0(); }
        __syncthreads();
        // buffer (buf+2)%3 was read at iter s-1; the barrier above drained it
        if (s + 2 < NS) {
            int nb2 = buf + 2; if (nb2 >= 3) nb2 -= 3;
            issue(s + 2, nb2);
        }
        const uint32_t sa = ab + buf * STAGEB;
        const uint32_t sb = sa + ABYTES;
        #pragma unroll
        for (int s4 = 0; s4 < 4; s4++) {
            const int xcol = s4 * 32 + lc * 16;
            uint32_t a[4][4];
            #pragma unroll
            for (int mm = 0; mm < 4; mm++) {
                int row = wm + mm * 16 + lr;
                uint32_t addr = sa + row * 128 + (xcol ^ ((row & 7) * 16));
                ldsm4(a[mm][0], a[mm][1], a[mm][2], a[mm][3], addr);
            }
            #pragma unroll
            for (int nb = 0; nb < 4; nb++) {
                int row = wn + nb * 16 + lr;
                uint32_t addr = sb + row * 128 + (xcol ^ ((row & 7) * 16));
                uint32_t b0, b1, b2, b3;
                ldsm4(b0, b1, b2, b3, addr);
                #pragma unroll
                for (int mm = 0; mm < 4; mm++) {
                    mma_bf16(acc[mm][2 * nb],     a[mm][0], a[mm][1], a[mm][2], a[mm][3], b0, b2);
                    mma_bf16(acc[mm][2 * nb + 1], a[mm][0], a[mm][1], a[mm][2], a[mm][3], b1, b3);
                }
            }
        }
        if (++buf == 3) buf = 0;
    }

    const int qr = lane >> 2;
    const int qc = (lane & 3) * 2;

    if (EPI == 0) {
        float* Cp = C + (size_t)pass * XD * XD;
        #pragma unroll
        for (int mm = 0; mm < 4; mm++) {
            int r = m0 + wm + mm * 16 + qr;
            #pragma unroll
            for (int j = 0; j < 8; j++) {
                int c = n0 + wn + j * 8 + qc;
                *(float2*)&Cp[(size_t)r * XD + c]       = make_float2(acc[mm][j][0], acc[mm][j][1]);
                *(float2*)&Cp[(size_t)(r + 8) * XD + c] = make_float2(acc[mm][j][2], acc[mm][j][3]);
            }
        }
    } else {
        // fused row-dot: g_r[i] += sum_c x[i][c] * P_tile[i][c]
        float pr[8];
        #pragma unroll
        for (int q = 0; q < 8; q++) pr[q] = 0.f;
        #pragma unroll
        for (int mm = 0; mm < 4; mm++) {
            int r = m0 + wm + mm * 16 + qr;
            #pragma unroll
            for (int j = 0; j < 8; j++) {
                int c = n0 + wn + j * 8 + qc;
                float2 x0 = *(const float2*)&xx[(size_t)r * XD + c];
                float2 x1 = *(const float2*)&xx[(size_t)(r + 8) * XD + c];
                pr[2 * mm]     += acc[mm][j][0] * x0.x + acc[mm][j][1] * x0.y;
                pr[2 * mm + 1] += acc[mm][j][2] * x1.x + acc[mm][j][3] * x1.y;
            }
        }
        #pragma unroll
        for (int q = 0; q < 8; q++) {
            pr[q] += __shfl_xor_sync(0xFFFFFFFFu, pr[q], 1);
            pr[q] += __shfl_xor_sync(0xFFFFFFFFu, pr[q], 2);
        }
        red[tid] = 0.f;
        __syncthreads();
        if ((lane & 3) == 0) {
            #pragma unroll
            for (int mm = 0; mm < 4; mm++) {
                atomicAdd(&red[wm + mm * 16 + qr],     pr[2 * mm]);
                atomicAdd(&red[wm + mm * 16 + qr + 8], pr[2 * mm + 1]);
            }
        }
        __syncthreads();
        atomicAdd(&C[m0 + tid], red[tid]);
    }
}

// ---------------------------------------------------------------------------
// Merged transpose + bf16 hi/lo split for Wq and Wk (blockIdx.z selects)
// ---------------------------------------------------------------------------
__global__ void transpose_ext2(const float* __restrict__ in0, __nv_bfloat16* __restrict__ out0,
                               const float* __restrict__ in1, __nv_bfloat16* __restrict__ out1) {
    __shared__ float t[32][33];
    const float* in = blockIdx.z ? in1 : in0;
    __nv_bfloat16* out = blockIdx.z ? out1 : out0;
    int bx = blockIdx.x * 32, by = blockIdx.y * 32;
    #pragma unroll
    for (int j = 0; j < 32; j += 8)
        t[threadIdx.y + j][threadIdx.x] = in[(size_t)(by + threadIdx.y + j) * XD + bx + threadIdx.x];
    __syncthreads();
    #pragma unroll
    for (int j = 0; j < 32; j += 8) {
        float v = t[threadIdx.x][threadIdx.y + j];
        __nv_bfloat16 h, l;
        split1(v, h, l);
        size_t r = bx + threadIdx.y + j;
        int c = by + threadIdx.x;
        out[r * KE2 + c]      = h;
        out[r * KE2 + XD + c] = l;
    }
}

// ---------------------------------------------------------------------------
// Scan: per-chunk column sums, then writeXs computes its own offsets inline
// ---------------------------------------------------------------------------
__global__ void colsum_kernel(const float* __restrict__ x) {
    int col = blockIdx.x * 256 + threadIdx.x;
    int ch  = blockIdx.y;
    const float* p = x + (size_t)ch * RPC * XD + col;
    float s = 0.f;
    #pragma unroll 8
    for (int r = 0; r < RPC; r++) s += p[(size_t)r * XD];
    g_part[ch * XD + col] = s;
}
__global__ void writeXs_ext(const float* __restrict__ x) {
    int col = blockIdx.x * 256 + threadIdx.x;
    int ch  = blockIdx.y;
    // zero g_r on the side (8192 of 65536 threads)
    int flat = (ch * gridDim.x + blockIdx.x) * 256 + threadIdx.x;
    if (flat < NR) g_r[flat] = 0.f;
    float run = 0.f;
    for (int c = 0; c < ch; c++) run += g_part[c * XD + col];
    #pragma unroll 4
    for (int r = 0; r < RPC; r++) {
        size_t row = (size_t)ch * RPC + r;
        __nv_bfloat16 h, l;
        split1(run, h, l);
        g_Xse[row * KE2 + col]      = h;
        g_Xse[row * KE2 + XD + col] = l;
        run += x[row * XD + col];
    }
}

// ---------------------------------------------------------------------------
// Sum the 3 M partials, split to [hi|lo] ext
// ---------------------------------------------------------------------------
__global__ void ext_sum3(__nv_bfloat16* __restrict__ out) {
    const size_t row = blockIdx.x;
    const int c = threadIdx.x * 4;
    const size_t base = row * XD + c;
    float4 a = *(const float4*)&g_Mpart[base];
    float4 b = *(const float4*)&g_Mpart[(size_t)XD * XD + base];
    float4 d = *(const float4*)&g_Mpart[2 * (size_t)XD * XD + base];
    float v[4] = {a.x + b.x + d.x, a.y + b.y + d.y, a.z + b.z + d.z, a.w + b.w + d.w};
    unsigned short hb[4], lb[4];
    #pragma unroll
    for (int i = 0; i < 4; i++) {
        __nv_bfloat16 h, l;
        split1(v[i], h, l);
        hb[i] = *reinterpret_cast<unsigned short*>(&h);
        lb[i] = *reinterpret_cast<unsigned short*>(&l);
    }
    unsigned short* ob = reinterpret_cast<unsigned short*>(out) + row * KE2;
    *(ushort4*)(ob + c)      = make_ushort4(hb[0], hb[1], hb[2], hb[3]);
    *(ushort4*)(ob + XD + c) = make_ushort4(lb[0], lb[1], lb[2], lb[3]);
}

// ---------------------------------------------------------------------------
// Small vectors: u = Wq^T bk, w = Wk^T bq, c0 = bq.bk
// ---------------------------------------------------------------------------
__global__ void smallvec_part_kernel(const float* __restrict__ Wq,
                                     const float* __restrict__ Wk,
                                     const float* __restrict__ bk,
                                     const float* __restrict__ bq) {
    int a  = blockIdx.x * 256 + threadIdx.x;
    int hb = blockIdx.y;
    float su = 0.f, sw = 0.f;
    #pragma unroll 4
    for (int h = hb * 128; h < hb * 128 + 128; h++) {
        su += Wq[(size_t)h * XD + a] * bk[h];
        sw += Wk[(size_t)h * XD + a] * bq[h];
    }
    g_upart[hb * XD + a] = su;
    g_wpart[hb * XD + a] = sw;
}
__global__ void smallvec_reduce_kernel() {
    int a = blockIdx.x * 256 + threadIdx.x;
    float su = 0.f, sw = 0.f;
    #pragma unroll
    for (int p = 0; p < 8; p++) { su += g_upart[p * XD + a]; sw += g_wpart[p * XD + a]; }
    g_u[a] = su;
    g_w[a] = sw;
}
__global__ void c0_kernel(const float* __restrict__ bq, const float* __restrict__ bk) {
    __shared__ float red[256];
    float s = 0.f;
    for (int i = threadIdx.x; i < XD; i += 256) s += bq[i] * bk[i];
    red[threadIdx.x] = s;
    __syncthreads();
    for (int st = 128; st > 0; st >>= 1) {
        if (threadIdx.x < st) red[threadIdx.x] += red[threadIdx.x + st];
        __syncthreads();
    }
    if (threadIdx.x == 0) g_c0 = red[0];
}

// ---------------------------------------------------------------------------
// Per-row dots: e_i = u.x_i, d_i = w.x_i
// ---------------------------------------------------------------------------
__global__ void rowdots_kernel(const float* __restrict__ x) {
    const int i = blockIdx.x;
    const int tid = threadIdx.x;
    float4 xv = *(const float4*)&x[(size_t)i * XD + tid * 4];
    float4 uv = *(const float4*)&g_u[tid * 4];
    float4 wv = *(const float4*)&g_w[tid * 4];
    float e = xv.x * uv.x + xv.y * uv.y + xv.z * uv.z + xv.w * uv.w;
    float d = xv.x * wv.x + xv.y * wv.y + xv.z * wv.z + xv.w * wv.w;
    #pragma unroll
    for (int off = 16; off > 0; off >>= 1) {
        e += __shfl_xor_sync(0xFFFFFFFFu, e, off);
        d += __shfl_xor_sync(0xFFFFFFFFu, d, off);
    }
    __shared__ float se[8], sd[8];
    if ((tid & 31) == 0) { se[tid >> 5] = e; sd[tid >> 5] = d; }
    __syncthreads();
    if (tid == 0) {
        float te = 0.f, td = 0.f;
        #pragma unroll
        for (int q = 0; q < 8; q++) { te += se[q]; td += sd[q]; }
        g_e[i] = te;
        g_d[i] = td;
    }
}

// ---------------------------------------------------------------------------
// Exclusive scan of d (8192 scalars) -> s
// ---------------------------------------------------------------------------
__global__ void dscan_kernel() {
    __shared__ float bs[1024];
    const int t = threadIdx.x;
    float v[8];
    float sum = 0.f;
    #pragma unroll
    for (int k = 0; k < 8; k++) { v[k] = g_d[t * 8 + k]; sum += v[k]; }
    bs[t] = sum;
    __syncthreads();
    // inclusive Hillis-Steele scan over block sums
    for (int off = 1; off < 1024; off <<= 1) {
        float tv = (t >= off) ? bs[t - off] : 0.f;
        __syncthreads();
        bs[t] += tv;
        __syncthreads();
    }
    float run = bs[t] - sum;  // exclusive offset for this thread's 8 values
    #pragma unroll
    for (int k = 0; k < 8; k++) {
        g_s[t * 8 + k] = run;
        run += v[k];
    }
}

// ---------------------------------------------------------------------------
// Finalize: out[i,:] = g_r[i] + i*(e_i + c0) + s_i
// ---------------------------------------------------------------------------
__global__ void finalize_kernel(float* __restrict__ out) {
    const int i = blockIdx.x;
    const float r = g_r[i] + (float)i * (g_e[i] + g_c0) + g_s[i];
    float4 rv = make_float4(r, r, r, r);
    *(float4*)&out[(size_t)i * XD + threadIdx.x * 4] = rv;
}

// ---------------------------------------------------------------------------
// kernel_launch — inputs: x, Wk, bk, Wv, bv, Wq, bq  (Wv/bv unused: V:=ones)
// ---------------------------------------------------------------------------
extern "C" void kernel_launch(void* const* d_in, const int* in_sizes, int n_in,
                              void* d_out, int out_size) {
    const float* x  = (const float*)d_in[0];
    const float* Wk = (const float*)d_in[1];
    const float* bk = (const float*)d_in[2];
    const float* Wq = (const float*)d_in[5];
    const float* bq = (const float*)d_in[6];
    float* out = (float*)d_out;

    __nv_bfloat16 *Xse, *Me, *WqTe, *WkTe;
    float *Mpart, *r;
    cudaGetSymbolAddress((void**)&Xse,   g_Xse);
    cudaGetSymbolAddress((void**)&Me,    g_Me);
    cudaGetSymbolAddress((void**)&WqTe,  g_WqTe);
    cudaGetSymbolAddress((void**)&WkTe,  g_WkTe);
    cudaGetSymbolAddress((void**)&Mpart, g_Mpart);
    cudaGetSymbolAddress((void**)&r,     g_r);

    cudaFuncSetAttribute(gemm_ext<0>, cudaFuncAttributeMaxDynamicSharedMemorySize, GSMEM);
    cudaFuncSetAttribute(gemm_ext<1>, cudaFuncAttributeMaxDynamicSharedMemorySize, GSMEM);

    // 1) transpose + split both weight matrices
    transpose_ext2<<<dim3(32, 32, 2), dim3(32, 8)>>>(Wq, WqTe, Wk, WkTe);

    // 2) M = Wq^T Wk (3 split passes -> partials), then sum+split to ext
    gemm_ext<0><<<dim3(XD / 128, XD / 256, 3), 256, GSMEM>>>(WqTe, WkTe, Mpart, nullptr);
    ext_sum3<<<XD, 256>>>(Me);

    // 3) prefix sum of x -> Xse ext (offsets computed inline; also zeroes g_r)
    colsum_kernel<<<dim3(XD / 256, CHUNKS), 256>>>(x);
    writeXs_ext<<<dim3(XD / 256, CHUNKS), 256>>>(x);

    // 4) fused P-GEMM + row-dot: g_r[i] = sum_a x[i][a] * (Xs M^T)[i][a]
    gemm_ext<1><<<dim3(XD / 128, NR / 256, 3), 256, GSMEM>>>(Xse, Me, r, x);

    // 5) u, w, c0, per-row dots e/d, scalar scan of d
    c0_kernel<<<1, 256>>>(bq, bk);
    smallvec_part_kernel<<<dim3(XD / 256, 8), 256>>>(Wq, Wk, bk, bq);
    smallvec_reduce_kernel<<<XD / 256, 256>>>();
    rowdots_kernel<<<NR, 256>>>(x);
    dscan_kernel<<<1, 1024>>>();

    // 6) broadcast
    finalize_kernel<<<NR, 256>>>(out);
}

// round 6
// speedup vs baseline: 1.3821x; 1.2376x over previous
#include <cuda_runtime.h>
#include <cuda_fp16.h>
#include <cstdint>

// Problem constants (N=8192, X=H=Y=1024)
#define NR 8192
#define XD 1024
#define KE2 2048           // [hi | lo*4096] extended-K storage (fp16)
#define CHUNKS 64
#define RPC 128
#define LO_SCALE 4096.0f
#define LO_INV   2.44140625e-4f   // 1/4096

// ---------------------------------------------------------------------------
// Device scratch (allocation-free rule)
// ---------------------------------------------------------------------------
__device__ __half g_Xse [(size_t)NR * KE2];   // ext [hi|lo*s] of Xs
__device__ __half g_WqTe[(size_t)XD * KE2];   // ext [hi|lo*s] of Wq^T
__device__ __half g_WkTe[(size_t)XD * KE2];   // ext [hi|lo*s] of Wk^T
__device__ float g_Mpart[3 * (size_t)XD * XD];// per-pass partials of M (raw)
__device__ __half g_Me[(size_t)XD * KE2];     // ext [hi|lo*s] of M
__device__ float g_r[NR];                     // fused row-dot accumulators
__device__ float g_e[NR];                     // e_i = u . x_i
__device__ float g_d[NR];                     // d_i = w . x_i
__device__ float g_s[NR];                     // s_i = sum_{j<i} d_j
__device__ float g_part[CHUNKS * XD];
__device__ float g_upart[8 * XD];
__device__ float g_wpart[8 * XD];
__device__ float g_u[XD];
__device__ float g_w[XD];
__device__ float g_c0;

// ---------------------------------------------------------------------------
// PTX helpers (base sm_80+ ISA only)
// ---------------------------------------------------------------------------
__device__ __forceinline__ uint32_t smem_u32(const void* p) {
    uint32_t a;
    asm("{ .reg .u64 t; cvta.to.shared.u64 t, %1; cvt.u32.u64 %0, t; }" : "=r"(a) : "l"(p));
    return a;
}
#define CP_ASYNC16(dst, src) \
    asm volatile("cp.async.cg.shared.global [%0], [%1], 16;" :: "r"(dst), "l"(src))
#define CP_COMMIT() asm volatile("cp.async.commit_group;" ::: "memory")
#define CP_WAIT1()  asm volatile("cp.async.wait_group 1;" ::: "memory")
#define CP_WAIT0()  asm volatile("cp.async.wait_group 0;" ::: "memory")

__device__ __forceinline__ void ldsm4(uint32_t& r0, uint32_t& r1, uint32_t& r2,
                                      uint32_t& r3, uint32_t addr) {
    asm volatile("ldmatrix.sync.aligned.m8n8.x4.shared.b16 {%0,%1,%2,%3}, [%4];"
                 : "=r"(r0), "=r"(r1), "=r"(r2), "=r"(r3) : "r"(addr));
}
__device__ __forceinline__ void mma_f16(float* c, uint32_t a0, uint32_t a1,
                                        uint32_t a2, uint32_t a3,
                                        uint32_t b0, uint32_t b1) {
    asm volatile(
        "mma.sync.aligned.m16n8k16.row.col.f32.f16.f16.f32 "
        "{%0,%1,%2,%3}, {%4,%5,%6,%7}, {%8,%9}, {%0,%1,%2,%3};"
        : "+f"(c[0]), "+f"(c[1]), "+f"(c[2]), "+f"(c[3])
        : "r"(a0), "r"(a1), "r"(a2), "r"(a3), "r"(b0), "r"(b1));
}
__device__ __forceinline__ uint32_t swz(uint32_t b) { return b ^ ((b >> 3) & 0x70); }

__device__ __forceinline__ void split1(float v, __half& h, __half& l) {
    h = __float2half_rn(v);
    l = __float2half_rn((v - __half2float(h)) * LO_SCALE);
}

// ---------------------------------------------------------------------------
// fp16-split GEMM, passes via blockIdx.z:
//   pass 0: (hi,hi)   pass 1: (lo*s, hi)   pass 2: (hi, lo*s)
// Block tile 256x128, 8 warps of 64x64, BK=64, 3-stage cp.async.
// EPI=0: raw per-pass store into Mpart[pass] (scaling applied in ext_sum3).
// EPI=1: fused row-dot (x . P_tile), pass>0 scaled by LO_INV, atomicAdd to g_r.
// ---------------------------------------------------------------------------
#define BK 64
#define NS 16                         // K-stages per pass (1024/64)
#define ABYTES (256 * BK * 2)         // 32 KB A stage
#define BBYTES (128 * BK * 2)         // 16 KB B stage
#define STAGEB (ABYTES + BBYTES)      // 48 KB
#define GSMEM (1024 + 3 * STAGEB)     // ~145 KB

template <int EPI>
__global__ void __launch_bounds__(256, 1)
gemm_ext(const __half* __restrict__ A,
         const __half* __restrict__ B,
         float* __restrict__ C,
         const float* __restrict__ xx) {
    extern __shared__ char smem_raw[];
    __shared__ float red[256];
    uint32_t raw = smem_u32(smem_raw);
    uint32_t ab = (raw + 1023u) & ~1023u;

    const int tid = threadIdx.x;
    const int wid = tid >> 5;
    const int lane = tid & 31;
    const int m0 = blockIdx.y * 256;
    const int n0 = blockIdx.x * 128;
    const int pass = blockIdx.z;
    const int aoff = (pass == 1) ? XD : 0;
    const int boff = (pass == 2) ? XD : 0;
    const int wm = (wid & 3) * 64;
    const int wn = (wid >> 2) * 64;

    const __half* gA = A + (size_t)m0 * KE2 + aoff;
    const __half* gB = B + (size_t)n0 * KE2 + boff;

    float acc[4][8][4];
    #pragma unroll
    for (int i = 0; i < 4; i++)
        #pragma unroll
        for (int j = 0; j < 8; j++)
            #pragma unroll
            for (int q = 0; q < 4; q++) acc[i][j][q] = 0.f;

    const int lrow = tid >> 3;
    const int lc16 = tid & 7;
    auto issue = [&](int s, int buf) {
        const uint32_t sa = ab + buf * STAGEB;
        const uint32_t sb = sa + ABYTES;
        const int kb = s * BK;
        #pragma unroll
        for (int i = 0; i < 8; i++) {
            int row = lrow + i * 32;
            uint32_t so = swz((uint32_t)(row * 128 + lc16 * 16));
            CP_ASYNC16(sa + so, gA + (size_t)row * KE2 + kb + lc16 * 8);
        }
        #pragma unroll
        for (int i = 0; i < 4; i++) {
            int row = lrow + i * 32;
            uint32_t so = swz((uint32_t)(row * 128 + lc16 * 16));
            CP_ASYNC16(sb + so, gB + (size_t)row * KE2 + kb + lc16 * 8);
        }
        CP_COMMIT();
    };
    issue(0, 0);
    issue(1, 1);

    const int lr = lane & 15;
    const int lc = lane >> 4;

    int buf = 0;
    for (int s = 0; s < NS; s++) {
        if (s + 1 < NS) { CP_WAIT1(); } else { CP_WAIT0(); }
        __syncthreads();
        if (s + 2 < NS) {
            int nb2 = buf + 2; if (nb2 >= 3) nb2 -= 3;
            issue(s + 2, nb2);
        }
        const uint32_t sa = ab + buf * STAGEB;
        const uint32_t sb = sa + ABYTES;
        #pragma unroll
        for (int s4 = 0; s4 < 4; s4++) {
            const int xcol = s4 * 32 + lc * 16;
            uint32_t a[4][4];
            #pragma unroll
            for (int mm = 0; mm < 4; mm++) {
                int row = wm + mm * 16 + lr;
                uint32_t addr = sa + row * 128 + (xcol ^ ((row & 7) * 16));
                ldsm4(a[mm][0], a[mm][1], a[mm][2], a[mm][3], addr);
            }
            #pragma unroll
            for (int nb = 0; nb < 4; nb++) {
                int row = wn + nb * 16 + lr;
                uint32_t addr = sb + row * 128 + (xcol ^ ((row & 7) * 16));
                uint32_t b0, b1, b2, b3;
                ldsm4(b0, b1, b2, b3, addr);
                #pragma unroll
                for (int mm = 0; mm < 4; mm++) {
                    mma_f16(acc[mm][2 * nb],     a[mm][0], a[mm][1], a[mm][2], a[mm][3], b0, b2);
                    mma_f16(acc[mm][2 * nb + 1], a[mm][0], a[mm][1], a[mm][2], a[mm][3], b1, b3);
                }
            }
        }
        if (++buf == 3) buf = 0;
    }

    const int qr = lane >> 2;
    const int qc = (lane & 3) * 2;

    if (EPI == 0) {
        float* Cp = C + (size_t)pass * XD * XD;
        #pragma unroll
        for (int mm = 0; mm < 4; mm++) {
            int r = m0 + wm + mm * 16 + qr;
            #pragma unroll
            for (int j = 0; j < 8; j++) {
                int c = n0 + wn + j * 8 + qc;
                *(float2*)&Cp[(size_t)r * XD + c]       = make_float2(acc[mm][j][0], acc[mm][j][1]);
                *(float2*)&Cp[(size_t)(r + 8) * XD + c] = make_float2(acc[mm][j][2], acc[mm][j][3]);
            }
        }
    } else {
        // fused row-dot: g_r[i] += scale * sum_c x[i][c] * P_tile[i][c]
        const float scale = (pass == 0) ? 1.f : LO_INV;
        float pr[8];
        #pragma unroll
        for (int q = 0; q < 8; q++) pr[q] = 0.f;
        #pragma unroll
        for (int mm = 0; mm < 4; mm++) {
            int r = m0 + wm + mm * 16 + qr;
            #pragma unroll
            for (int j = 0; j < 8; j++) {
                int c = n0 + wn + j * 8 + qc;
                float2 x0 = *(const float2*)&xx[(size_t)r * XD + c];
                float2 x1 = *(const float2*)&xx[(size_t)(r + 8) * XD + c];
                pr[2 * mm]     += acc[mm][j][0] * x0.x + acc[mm][j][1] * x0.y;
                pr[2 * mm + 1] += acc[mm][j][2] * x1.x + acc[mm][j][3] * x1.y;
            }
        }
        #pragma unroll
        for (int q = 0; q < 8; q++) {
            pr[q] *= scale;
            pr[q] += __shfl_xor_sync(0xFFFFFFFFu, pr[q], 1);
            pr[q] += __shfl_xor_sync(0xFFFFFFFFu, pr[q], 2);
        }
        red[tid] = 0.f;
        __syncthreads();
        if ((lane & 3) == 0) {
            #pragma unroll
            for (int mm = 0; mm < 4; mm++) {
                atomicAdd(&red[wm + mm * 16 + qr],     pr[2 * mm]);
                atomicAdd(&red[wm + mm * 16 + qr + 8], pr[2 * mm + 1]);
            }
        }
        __syncthreads();
        atomicAdd(&C[m0 + tid], red[tid]);
    }
}

// ---------------------------------------------------------------------------
// Merged transpose + fp16 hi/lo split for Wq and Wk (blockIdx.z selects)
// ---------------------------------------------------------------------------
__global__ void transpose_ext2(const float* __restrict__ in0, __half* __restrict__ out0,
                               const float* __restrict__ in1, __half* __restrict__ out1) {
    __shared__ float t[32][33];
    const float* in = blockIdx.z ? in1 : in0;
    __half* out = blockIdx.z ? out1 : out0;
    int bx = blockIdx.x * 32, by = blockIdx.y * 32;
    #pragma unroll
    for (int j = 0; j < 32; j += 8)
        t[threadIdx.y + j][threadIdx.x] = in[(size_t)(by + threadIdx.y + j) * XD + bx + threadIdx.x];
    __syncthreads();
    #pragma unroll
    for (int j = 0; j < 32; j += 8) {
        float v = t[threadIdx.x][threadIdx.y + j];
        __half h, l;
        split1(v, h, l);
        size_t r = bx + threadIdx.y + j;
        int c = by + threadIdx.x;
        out[r * KE2 + c]      = h;
        out[r * KE2 + XD + c] = l;
    }
}

// ---------------------------------------------------------------------------
// Scan: per-chunk column sums, writeXs computes offsets inline
// ---------------------------------------------------------------------------
__global__ void colsum_kernel(const float* __restrict__ x) {
    int col = blockIdx.x * 256 + threadIdx.x;
    int ch  = blockIdx.y;
    const float* p = x + (size_t)ch * RPC * XD + col;
    float s = 0.f;
    #pragma unroll 8
    for (int r = 0; r < RPC; r++) s += p[(size_t)r * XD];
    g_part[ch * XD + col] = s;
}
__global__ void writeXs_ext(const float* __restrict__ x) {
    int col = blockIdx.x * 256 + threadIdx.x;
    int ch  = blockIdx.y;
    int flat = (ch * gridDim.x + blockIdx.x) * 256 + threadIdx.x;
    if (flat < NR) g_r[flat] = 0.f;
    float run = 0.f;
    for (int c = 0; c < ch; c++) run += g_part[c * XD + col];
    #pragma unroll 4
    for (int r = 0; r < RPC; r++) {
        size_t row = (size_t)ch * RPC + r;
        __half h, l;
        split1(run, h, l);
        g_Xse[row * KE2 + col]      = h;
        g_Xse[row * KE2 + XD + col] = l;
        run += x[row * XD + col];
    }
}

// ---------------------------------------------------------------------------
// Sum the 3 M partials (unscale lo passes), split to fp16 [hi|lo*s]
// ---------------------------------------------------------------------------
__global__ void ext_sum3(__half* __restrict__ out) {
    const size_t row = blockIdx.x;
    const int c = threadIdx.x * 4;
    const size_t base = row * XD + c;
    float4 a = *(const float4*)&g_Mpart[base];
    float4 b = *(const float4*)&g_Mpart[(size_t)XD * XD + base];
    float4 d = *(const float4*)&g_Mpart[2 * (size_t)XD * XD + base];
    float v[4] = {a.x + (b.x + d.x) * LO_INV, a.y + (b.y + d.y) * LO_INV,
                  a.z + (b.z + d.z) * LO_INV, a.w + (b.w + d.w) * LO_INV};
    unsigned short hb[4], lb[4];
    #pragma unroll
    for (int i = 0; i < 4; i++) {
        __half h, l;
        split1(v[i], h, l);
        hb[i] = *reinterpret_cast<unsigned short*>(&h);
        lb[i] = *reinterpret_cast<unsigned short*>(&l);
    }
    unsigned short* ob = reinterpret_cast<unsigned short*>(out) + row * KE2;
    *(ushort4*)(ob + c)      = make_ushort4(hb[0], hb[1], hb[2], hb[3]);
    *(ushort4*)(ob + XD + c) = make_ushort4(lb[0], lb[1], lb[2], lb[3]);
}

// ---------------------------------------------------------------------------
// Small vectors: u = Wq^T bk, w = Wk^T bq, c0 = bq.bk
// ---------------------------------------------------------------------------
__global__ void smallvec_part_kernel(const float* __restrict__ Wq,
                                     const float* __restrict__ Wk,
                                     const float* __restrict__ bk,
                                     const float* __restrict__ bq) {
    int a  = blockIdx.x * 256 + threadIdx.x;
    int hb = blockIdx.y;
    float su = 0.f, sw = 0.f;
    #pragma unroll 4
    for (int h = hb * 128; h < hb * 128 + 128; h++) {
        su += Wq[(size_t)h * XD + a] * bk[h];
        sw += Wk[(size_t)h * XD + a] * bq[h];
    }
    g_upart[hb * XD + a] = su;
    g_wpart[hb * XD + a] = sw;
}
__global__ void smallvec_reduce_kernel() {
    int a = blockIdx.x * 256 + threadIdx.x;
    float su = 0.f, sw = 0.f;
    #pragma unroll
    for (int p = 0; p < 8; p++) { su += g_upart[p * XD + a]; sw += g_wpart[p * XD + a]; }
    g_u[a] = su;
    g_w[a] = sw;
}
__global__ void c0_kernel(const float* __restrict__ bq, const float* __restrict__ bk) {
    __shared__ float red[256];
    float s = 0.f;
    for (int i = threadIdx.x; i < XD; i += 256) s += bq[i] * bk[i];
    red[threadIdx.x] = s;
    __syncthreads();
    for (int st = 128; st > 0; st >>= 1) {
        if (threadIdx.x < st) red[threadIdx.x] += red[threadIdx.x + st];
        __syncthreads();
    }
    if (threadIdx.x == 0) g_c0 = red[0];
}

// ---------------------------------------------------------------------------
// Per-row dots: e_i = u.x_i, d_i = w.x_i
// ---------------------------------------------------------------------------
__global__ void rowdots_kernel(const float* __restrict__ x) {
    const int i = blockIdx.x;
    const int tid = threadIdx.x;
    float4 xv = *(const float4*)&x[(size_t)i * XD + tid * 4];
    float4 uv = *(const float4*)&g_u[tid * 4];
    float4 wv = *(const float4*)&g_w[tid * 4];
    float e = xv.x * uv.x + xv.y * uv.y + xv.z * uv.z + xv.w * uv.w;
    float d = xv.x * wv.x + xv.y * wv.y + xv.z * wv.z + xv.w * wv.w;
    #pragma unroll
    for (int off = 16; off > 0; off >>= 1) {
        e += __shfl_xor_sync(0xFFFFFFFFu, e, off);
        d += __shfl_xor_sync(0xFFFFFFFFu, d, off);
    }
    __shared__ float se[8], sd[8];
    if ((tid & 31) == 0) { se[tid >> 5] = e; sd[tid >> 5] = d; }
    __syncthreads();
    if (tid == 0) {
        float te = 0.f, td = 0.f;
        #pragma unroll
        for (int q = 0; q < 8; q++) { te += se[q]; td += sd[q]; }
        g_e[i] = te;
        g_d[i] = td;
    }
}

// ---------------------------------------------------------------------------
// Exclusive scan of d (8192 scalars) -> s
// ---------------------------------------------------------------------------
__global__ void dscan_kernel() {
    __shared__ float bs[1024];
    const int t = threadIdx.x;
    float v[8];
    float sum = 0.f;
    #pragma unroll
    for (int k = 0; k < 8; k++) { v[k] = g_d[t * 8 + k]; sum += v[k]; }
    bs[t] = sum;
    __syncthreads();
    for (int off = 1; off < 1024; off <<= 1) {
        float tv = (t >= off) ? bs[t - off] : 0.f;
        __syncthreads();
        bs[t] += tv;
        __syncthreads();
    }
    float run = bs[t] - sum;
    #pragma unroll
    for (int k = 0; k < 8; k++) {
        g_s[t * 8 + k] = run;
        run += v[k];
    }
}

// ---------------------------------------------------------------------------
// Finalize: out[i,:] = g_r[i] + i*(e_i + c0) + s_i
// ---------------------------------------------------------------------------
__global__ void finalize_kernel(float* __restrict__ out) {
    const int i = blockIdx.x;
    const float r = g_r[i] + (float)i * (g_e[i] + g_c0) + g_s[i];
    float4 rv = make_float4(r, r, r, r);
    *(float4*)&out[(size_t)i * XD + threadIdx.x * 4] = rv;
}

// ---------------------------------------------------------------------------
// kernel_launch — inputs: x, Wk, bk, Wv, bv, Wq, bq  (Wv/bv unused: V:=ones)
// ---------------------------------------------------------------------------
extern "C" void kernel_launch(void* const* d_in, const int* in_sizes, int n_in,
                              void* d_out, int out_size) {
    const float* x  = (const float*)d_in[0];
    const float* Wk = (const float*)d_in[1];
    const float* bk = (const float*)d_in[2];
    const float* Wq = (const float*)d_in[5];
    const float* bq = (const float*)d_in[6];
    float* out = (float*)d_out;

    __half *Xse, *Me, *WqTe, *WkTe;
    float *Mpart, *r;
    cudaGetSymbolAddress((void**)&Xse,   g_Xse);
    cudaGetSymbolAddress((void**)&Me,    g_Me);
    cudaGetSymbolAddress((void**)&WqTe,  g_WqTe);
    cudaGetSymbolAddress((void**)&WkTe,  g_WkTe);
    cudaGetSymbolAddress((void**)&Mpart, g_Mpart);
    cudaGetSymbolAddress((void**)&r,     g_r);

    cudaFuncSetAttribute(gemm_ext<0>, cudaFuncAttributeMaxDynamicSharedMemorySize, GSMEM);
    cudaFuncSetAttribute(gemm_ext<1>, cudaFuncAttributeMaxDynamicSharedMemorySize, GSMEM);

    // 1) transpose + split both weight matrices
    transpose_ext2<<<dim3(32, 32, 2), dim3(32, 8)>>>(Wq, WqTe, Wk, WkTe);

    // 2) M = Wq^T Wk — full 3-pass split (keeps M at ~1e-7)
    gemm_ext<0><<<dim3(XD / 128, XD / 256, 3), 256, GSMEM>>>(WqTe, WkTe, Mpart, nullptr);
    ext_sum3<<<XD, 256>>>(Me);

    // 3) prefix sum of x -> Xse ext (offsets inline; also zeroes g_r)
    colsum_kernel<<<dim3(XD / 256, CHUNKS), 256>>>(x);
    writeXs_ext<<<dim3(XD / 256, CHUNKS), 256>>>(x);

    // 4) fused P-GEMM + row-dot — 2-pass fp16 split (drops hi(Xs).lo(M) ~ 2e-4)
    gemm_ext<1><<<dim3(XD / 128, NR / 256, 2), 256, GSMEM>>>(Xse, Me, r, x);

    // 5) u, w, c0, per-row dots, scalar scan of d
    c0_kernel<<<1, 256>>>(bq, bk);
    smallvec_part_kernel<<<dim3(XD / 256, 8), 256>>>(Wq, Wk, bk, bq);
    smallvec_reduce_kernel<<<XD / 256, 256>>>();
    rowdots_kernel<<<NR, 256>>>(x);
    dscan_kernel<<<1, 1024>>>();

    // 6) broadcast
    finalize_kernel<<<NR, 256>>>(out);
}

// round 7
// speedup vs baseline: 1.9506x; 1.4114x over previous
#include <cuda_runtime.h>
#include <cuda_fp16.h>
#include <cstdint>

// Problem constants (N=8192, X=H=Y=1024)
#define NR 8192
#define XD 1024
#define KE2 2048           // [hi | lo*4096] layout for weight operands
#define CHUNKS 128
#define RPC 64
#define LO_SCALE 4096.0f
#define LO_INV   2.44140625e-4f   // 1/4096

// ---------------------------------------------------------------------------
// Device scratch (allocation-free rule)
// ---------------------------------------------------------------------------
__device__ __half g_Xsh [(size_t)NR * XD];    // hi(Xs) only
__device__ __half g_WqTe[(size_t)XD * KE2];   // ext [hi|lo*s] of Wq^T
__device__ __half g_WkTe[(size_t)XD * KE2];   // ext [hi|lo*s] of Wk^T
__device__ float g_Mpart[3 * (size_t)XD * XD];// per-pass partials of M (raw)
__device__ __half g_Mh[(size_t)XD * XD];      // hi(M) only
__device__ float g_r[NR];                     // fused row-dot accumulators
__device__ float g_e[NR];                     // e_i = u . x_i
__device__ float g_d[NR];                     // d_i = w . x_i
__device__ float g_s[NR];                     // s_i = sum_{j<i} d_j
__device__ float g_part[CHUNKS * XD];
__device__ float g_upart[8 * XD];
__device__ float g_wpart[8 * XD];
__device__ float g_u[XD];
__device__ float g_w[XD];
__device__ float g_c0;

// ---------------------------------------------------------------------------
// PTX helpers (base sm_80+ ISA only)
// ---------------------------------------------------------------------------
__device__ __forceinline__ uint32_t smem_u32(const void* p) {
    uint32_t a;
    asm("{ .reg .u64 t; cvta.to.shared.u64 t, %1; cvt.u32.u64 %0, t; }" : "=r"(a) : "l"(p));
    return a;
}
#define CP_ASYNC16(dst, src) \
    asm volatile("cp.async.cg.shared.global [%0], [%1], 16;" :: "r"(dst), "l"(src))
#define CP_COMMIT() asm volatile("cp.async.commit_group;" ::: "memory")
#define CP_WAIT1()  asm volatile("cp.async.wait_group 1;" ::: "memory")
#define CP_WAIT0()  asm volatile("cp.async.wait_group 0;" ::: "memory")

__device__ __forceinline__ void ldsm4(uint32_t& r0, uint32_t& r1, uint32_t& r2,
                                      uint32_t& r3, uint32_t addr) {
    asm volatile("ldmatrix.sync.aligned.m8n8.x4.shared.b16 {%0,%1,%2,%3}, [%4];"
                 : "=r"(r0), "=r"(r1), "=r"(r2), "=r"(r3) : "r"(addr));
}
__device__ __forceinline__ void mma_f16(float* c, uint32_t a0, uint32_t a1,
                                        uint32_t a2, uint32_t a3,
                                        uint32_t b0, uint32_t b1) {
    asm volatile(
        "mma.sync.aligned.m16n8k16.row.col.f32.f16.f16.f32 "
        "{%0,%1,%2,%3}, {%4,%5,%6,%7}, {%8,%9}, {%0,%1,%2,%3};"
        : "+f"(c[0]), "+f"(c[1]), "+f"(c[2]), "+f"(c[3])
        : "r"(a0), "r"(a1), "r"(a2), "r"(a3), "r"(b0), "r"(b1));
}
__device__ __forceinline__ uint32_t swz(uint32_t b) { return b ^ ((b >> 3) & 0x70); }

__device__ __forceinline__ void split1(float v, __half& h, __half& l) {
    h = __float2half_rn(v);
    l = __float2half_rn((v - __half2float(h)) * LO_SCALE);
}

// ---------------------------------------------------------------------------
// fp16-split GEMM. Operand row stride = ldk. Passes via blockIdx.z:
//   pass 0: (hi,hi)   pass 1: (lo*s, hi)   pass 2: (hi, lo*s)
// (offsets assume ldk==2048 for pass>0; P-GEMM always runs z=1 / pass 0)
// Block tile 256x128, 8 warps of 64x64, BK=64, 3-stage cp.async.
// EPI=0: raw per-pass store into Mpart[pass]. EPI=1: fused row-dot -> g_r.
// ---------------------------------------------------------------------------
#define BK 64
#define ABYTES (256 * BK * 2)         // 32 KB A stage
#define BBYTES (128 * BK * 2)         // 16 KB B stage
#define STAGEB (ABYTES + BBYTES)      // 48 KB
#define GSMEM (1024 + 3 * STAGEB)     // ~145 KB
#define NS 16                         // K-stages (1024/64)

template <int EPI>
__global__ void __launch_bounds__(256, 1)
gemm_ext(const __half* __restrict__ A,
         const __half* __restrict__ B,
         float* __restrict__ C,
         const float* __restrict__ xx,
         int ldk) {
    extern __shared__ char smem_raw[];
    __shared__ float red[256];
    uint32_t raw = smem_u32(smem_raw);
    uint32_t ab = (raw + 1023u) & ~1023u;

    const int tid = threadIdx.x;
    const int wid = tid >> 5;
    const int lane = tid & 31;
    const int m0 = blockIdx.y * 256;
    const int n0 = blockIdx.x * 128;
    const int pass = blockIdx.z;
    const int aoff = (pass == 1) ? XD : 0;
    const int boff = (pass == 2) ? XD : 0;
    const int wm = (wid & 3) * 64;
    const int wn = (wid >> 2) * 64;

    const __half* gA = A + (size_t)m0 * ldk + aoff;
    const __half* gB = B + (size_t)n0 * ldk + boff;

    float acc[4][8][4];
    #pragma unroll
    for (int i = 0; i < 4; i++)
        #pragma unroll
        for (int j = 0; j < 8; j++)
            #pragma unroll
            for (int q = 0; q < 4; q++) acc[i][j][q] = 0.f;

    const int lrow = tid >> 3;
    const int lc16 = tid & 7;
    auto issue = [&](int s, int buf) {
        const uint32_t sa = ab + buf * STAGEB;
        const uint32_t sb = sa + ABYTES;
        const int kb = s * BK;
        #pragma unroll
        for (int i = 0; i < 8; i++) {
            int row = lrow + i * 32;
            uint32_t so = swz((uint32_t)(row * 128 + lc16 * 16));
            CP_ASYNC16(sa + so, gA + (size_t)row * ldk + kb + lc16 * 8);
        }
        #pragma unroll
        for (int i = 0; i < 4; i++) {
            int row = lrow + i * 32;
            uint32_t so = swz((uint32_t)(row * 128 + lc16 * 16));
            CP_ASYNC16(sb + so, gB + (size_t)row * ldk + kb + lc16 * 8);
        }
        CP_COMMIT();
    };
    issue(0, 0);
    issue(1, 1);

    const int lr = lane & 15;
    const int lc = lane >> 4;

    int buf = 0;
    for (int s = 0; s < NS; s++) {
        if (s + 1 < NS) { CP_WAIT1(); } else { CP_WAIT0(); }
        __syncthreads();
        if (s + 2 < NS) {
            int nb2 = buf + 2; if (nb2 >= 3) nb2 -= 3;
            issue(s + 2, nb2);
        }
        const uint32_t sa = ab + buf * STAGEB;
        const uint32_t sb = sa + ABYTES;
        #pragma unroll
        for (int s4 = 0; s4 < 4; s4++) {
            const int xcol = s4 * 32 + lc * 16;
            uint32_t a[4][4];
            #pragma unroll
            for (int mm = 0; mm < 4; mm++) {
                int row = wm + mm * 16 + lr;
                uint32_t addr = sa + row * 128 + (xcol ^ ((row & 7) * 16));
                ldsm4(a[mm][0], a[mm][1], a[mm][2], a[mm][3], addr);
            }
            #pragma unroll
            for (int nb = 0; nb < 4; nb++) {
                int row = wn + nb * 16 + lr;
                uint32_t addr = sb + row * 128 + (xcol ^ ((row & 7) * 16));
                uint32_t b0, b1, b2, b3;
                ldsm4(b0, b1, b2, b3, addr);
                #pragma unroll
                for (int mm = 0; mm < 4; mm++) {
                    mma_f16(acc[mm][2 * nb],     a[mm][0], a[mm][1], a[mm][2], a[mm][3], b0, b2);
                    mma_f16(acc[mm][2 * nb + 1], a[mm][0], a[mm][1], a[mm][2], a[mm][3], b1, b3);
                }
            }
        }
        if (++buf == 3) buf = 0;
    }

    const int qr = lane >> 2;
    const int qc = (lane & 3) * 2;

    if (EPI == 0) {
        float* Cp = C + (size_t)pass * XD * XD;
        #pragma unroll
        for (int mm = 0; mm < 4; mm++) {
            int r = m0 + wm + mm * 16 + qr;
            #pragma unroll
            for (int j = 0; j < 8; j++) {
                int c = n0 + wn + j * 8 + qc;
                *(float2*)&Cp[(size_t)r * XD + c]       = make_float2(acc[mm][j][0], acc[mm][j][1]);
                *(float2*)&Cp[(size_t)(r + 8) * XD + c] = make_float2(acc[mm][j][2], acc[mm][j][3]);
            }
        }
    } else {
        // fused row-dot: g_r[i] += sum_c x[i][c] * P_tile[i][c]
        float pr[8];
        #pragma unroll
        for (int q = 0; q < 8; q++) pr[q] = 0.f;
        #pragma unroll
        for (int mm = 0; mm < 4; mm++) {
            int r = m0 + wm + mm * 16 + qr;
            #pragma unroll
            for (int j = 0; j < 8; j++) {
                int c = n0 + wn + j * 8 + qc;
                float2 x0 = *(const float2*)&xx[(size_t)r * XD + c];
                float2 x1 = *(const float2*)&xx[(size_t)(r + 8) * XD + c];
                pr[2 * mm]     += acc[mm][j][0] * x0.x + acc[mm][j][1] * x0.y;
                pr[2 * mm + 1] += acc[mm][j][2] * x1.x + acc[mm][j][3] * x1.y;
            }
        }
        #pragma unroll
        for (int q = 0; q < 8; q++) {
            pr[q] += __shfl_xor_sync(0xFFFFFFFFu, pr[q], 1);
            pr[q] += __shfl_xor_sync(0xFFFFFFFFu, pr[q], 2);
        }
        red[tid] = 0.f;
        __syncthreads();
        if ((lane & 3) == 0) {
            #pragma unroll
            for (int mm = 0; mm < 4; mm++) {
                atomicAdd(&red[wm + mm * 16 + qr],     pr[2 * mm]);
                atomicAdd(&red[wm + mm * 16 + qr + 8], pr[2 * mm + 1]);
            }
        }
        __syncthreads();
        atomicAdd(&C[m0 + tid], red[tid]);
    }
}

// ---------------------------------------------------------------------------
// Merged transpose + fp16 hi/lo split for Wq and Wk (blockIdx.z selects)
// ---------------------------------------------------------------------------
__global__ void transpose_ext2(const float* __restrict__ in0, __half* __restrict__ out0,
                               const float* __restrict__ in1, __half* __restrict__ out1) {
    __shared__ float t[32][33];
    const float* in = blockIdx.z ? in1 : in0;
    __half* out = blockIdx.z ? out1 : out0;
    int bx = blockIdx.x * 32, by = blockIdx.y * 32;
    #pragma unroll
    for (int j = 0; j < 32; j += 8)
        t[threadIdx.y + j][threadIdx.x] = in[(size_t)(by + threadIdx.y + j) * XD + bx + threadIdx.x];
    __syncthreads();
    #pragma unroll
    for (int j = 0; j < 32; j += 8) {
        float v = t[threadIdx.x][threadIdx.y + j];
        __half h, l;
        split1(v, h, l);
        size_t r = bx + threadIdx.y + j;
        int c = by + threadIdx.x;
        out[r * KE2 + c]      = h;
        out[r * KE2 + XD + c] = l;
    }
}

// ---------------------------------------------------------------------------
// Scan: per-chunk column sums, then writeXs computes offsets inline (hi only)
// ---------------------------------------------------------------------------
__global__ void colsum_kernel(const float* __restrict__ x) {
    int col = blockIdx.x * 256 + threadIdx.x;
    int ch  = blockIdx.y;
    const float* p = x + (size_t)ch * RPC * XD + col;
    float s0 = 0.f, s1 = 0.f;
    #pragma unroll 8
    for (int r = 0; r < RPC; r += 2) {
        s0 += p[(size_t)r * XD];
        s1 += p[(size_t)(r + 1) * XD];
    }
    g_part[ch * XD + col] = s0 + s1;
}
__global__ void writeXs_hi(const float* __restrict__ x) {
    int col = blockIdx.x * 256 + threadIdx.x;
    int ch  = blockIdx.y;
    int flat = (ch * gridDim.x + blockIdx.x) * 256 + threadIdx.x;
    if (flat < NR) g_r[flat] = 0.f;
    float run = 0.f;
    for (int c = 0; c < ch; c++) run += g_part[c * XD + col];
    #pragma unroll 4
    for (int r = 0; r < RPC; r++) {
        size_t row = (size_t)ch * RPC + r;
        g_Xsh[row * XD + col] = __float2half_rn(run);
        run += x[row * XD + col];
    }
}

// ---------------------------------------------------------------------------
// Sum the 3 M partials (unscale lo passes), store hi(M) fp16
// ---------------------------------------------------------------------------
__global__ void msum_hi(__half* __restrict__ out) {
    const size_t row = blockIdx.x;
    const int c = threadIdx.x * 4;
    const size_t base = row * XD + c;
    float4 a = *(const float4*)&g_Mpart[base];
    float4 b = *(const float4*)&g_Mpart[(size_t)XD * XD + base];
    float4 d = *(const float4*)&g_Mpart[2 * (size_t)XD * XD + base];
    unsigned short hb[4];
    float v[4] = {a.x + (b.x + d.x) * LO_INV, a.y + (b.y + d.y) * LO_INV,
                  a.z + (b.z + d.z) * LO_INV, a.w + (b.w + d.w) * LO_INV};
    #pragma unroll
    for (int i = 0; i < 4; i++) {
        __half h = __float2half_rn(v[i]);
        hb[i] = *reinterpret_cast<unsigned short*>(&h);
    }
    *(ushort4*)(reinterpret_cast<unsigned short*>(out) + row * XD + c) =
        make_ushort4(hb[0], hb[1], hb[2], hb[3]);
}

// ---------------------------------------------------------------------------
// Small vectors: u = Wq^T bk, w = Wk^T bq, c0 = bq.bk
// ---------------------------------------------------------------------------
__global__ void smallvec_part_kernel(const float* __restrict__ Wq,
                                     const float* __restrict__ Wk,
                                     const float* __restrict__ bk,
                                     const float* __restrict__ bq) {
    int a  = blockIdx.x * 256 + threadIdx.x;
    int hb = blockIdx.y;
    float su = 0.f, sw = 0.f;
    #pragma unroll 4
    for (int h = hb * 128; h < hb * 128 + 128; h++) {
        su += Wq[(size_t)h * XD + a] * bk[h];
        sw += Wk[(size_t)h * XD + a] * bq[h];
    }
    g_upart[hb * XD + a] = su;
    g_wpart[hb * XD + a] = sw;
}
__global__ void smallvec_reduce_kernel(const float* __restrict__ bq,
                                       const float* __restrict__ bk) {
    int a = blockIdx.x * 256 + threadIdx.x;
    float su = 0.f, sw = 0.f;
    #pragma unroll
    for (int p = 0; p < 8; p++) { su += g_upart[p * XD + a]; sw += g_wpart[p * XD + a]; }
    g_u[a] = su;
    g_w[a] = sw;
    // c0 via one warp of block 0
    if (blockIdx.x == 0 && threadIdx.x < 32) {
        float s = 0.f;
        for (int i = threadIdx.x; i < XD; i += 32) s += bq[i] * bk[i];
        #pragma unroll
        for (int off = 16; off > 0; off >>= 1)
            s += __shfl_xor_sync(0xFFFFFFFFu, s, off);
        if (threadIdx.x == 0) g_c0 = s;
    }
}

// ---------------------------------------------------------------------------
// Per-row dots: e_i = u.x_i, d_i = w.x_i
// ---------------------------------------------------------------------------
__global__ void rowdots_kernel(const float* __restrict__ x) {
    const int i = blockIdx.x;
    const int tid = threadIdx.x;
    float4 xv = *(const float4*)&x[(size_t)i * XD + tid * 4];
    float4 uv = *(const float4*)&g_u[tid * 4];
    float4 wv = *(const float4*)&g_w[tid * 4];
    float e = xv.x * uv.x + xv.y * uv.y + xv.z * uv.z + xv.w * uv.w;
    float d = xv.x * wv.x + xv.y * wv.y + xv.z * wv.z + xv.w * wv.w;
    #pragma unroll
    for (int off = 16; off > 0; off >>= 1) {
        e += __shfl_xor_sync(0xFFFFFFFFu, e, off);
        d += __shfl_xor_sync(0xFFFFFFFFu, d, off);
    }
    __shared__ float se[8], sd[8];
    if ((tid & 31) == 0) { se[tid >> 5] = e; sd[tid >> 5] = d; }
    __syncthreads();
    if (tid == 0) {
        float te = 0.f, td = 0.f;
        #pragma unroll
        for (int q = 0; q < 8; q++) { te += se[q]; td += sd[q]; }
        g_e[i] = te;
        g_d[i] = td;
    }
}

// ---------------------------------------------------------------------------
// Exclusive scan of d (8192 scalars) -> s, shfl-based
// ---------------------------------------------------------------------------
__global__ void dscan_kernel() {
    const int t = threadIdx.x;          // 1024 threads x 8 values
    const int lane = t & 31;
    const int warp = t >> 5;
    float v[8];
    float sum = 0.f;
    #pragma unroll
    for (int k = 0; k < 8; k++) { v[k] = g_d[t * 8 + k]; sum += v[k]; }
    // warp inclusive scan
    float sc = sum;
    #pragma unroll
    for (int off = 1; off < 32; off <<= 1) {
        float n = __shfl_up_sync(0xFFFFFFFFu, sc, off);
        if (lane >= off) sc += n;
    }
    __shared__ float wsum[32];
    if (lane == 31) wsum[warp] = sc;
    __syncthreads();
    if (warp == 0) {
        float ws = wsum[lane];
        #pragma unroll
        for (int off = 1; off < 32; off <<= 1) {
            float n = __shfl_up_sync(0xFFFFFFFFu, ws, off);
            if (lane >= off) ws += n;
        }
        wsum[lane] = ws;
    }
    __syncthreads();
    float run = (warp ? wsum[warp - 1] : 0.f) + (sc - sum);  // exclusive base
    #pragma unroll
    for (int k = 0; k < 8; k++) {
        g_s[t * 8 + k] = run;
        run += v[k];
    }
}

// ---------------------------------------------------------------------------
// Finalize: out[i,:] = g_r[i] + i*(e_i + c0) + s_i
// ---------------------------------------------------------------------------
__global__ void finalize_kernel(float* __restrict__ out) {
    const int i = blockIdx.x;
    const float r = g_r[i] + (float)i * (g_e[i] + g_c0) + g_s[i];
    float4 rv = make_float4(r, r, r, r);
    *(float4*)&out[(size_t)i * XD + threadIdx.x * 4] = rv;
}

// ---------------------------------------------------------------------------
// kernel_launch — inputs: x, Wk, bk, Wv, bv, Wq, bq  (Wv/bv unused: V:=ones)
// ---------------------------------------------------------------------------
extern "C" void kernel_launch(void* const* d_in, const int* in_sizes, int n_in,
                              void* d_out, int out_size) {
    const float* x  = (const float*)d_in[0];
    const float* Wk = (const float*)d_in[1];
    const float* bk = (const float*)d_in[2];
    const float* Wq = (const float*)d_in[5];
    const float* bq = (const float*)d_in[6];
    float* out = (float*)d_out;

    __half *Xsh, *Mh, *WqTe, *WkTe;
    float *Mpart, *r;
    cudaGetSymbolAddress((void**)&Xsh,   g_Xsh);
    cudaGetSymbolAddress((void**)&Mh,    g_Mh);
    cudaGetSymbolAddress((void**)&WqTe,  g_WqTe);
    cudaGetSymbolAddress((void**)&WkTe,  g_WkTe);
    cudaGetSymbolAddress((void**)&Mpart, g_Mpart);
    cudaGetSymbolAddress((void**)&r,     g_r);

    cudaFuncSetAttribute(gemm_ext<0>, cudaFuncAttributeMaxDynamicSharedMemorySize, GSMEM);
    cudaFuncSetAttribute(gemm_ext<1>, cudaFuncAttributeMaxDynamicSharedMemorySize, GSMEM);

    // 1) transpose + split both weight matrices
    transpose_ext2<<<dim3(32, 32, 2), dim3(32, 8)>>>(Wq, WqTe, Wk, WkTe);

    // 2) M = Wq^T Wk — full 3-pass split (fp32-accurate M), store hi(M)
    gemm_ext<0><<<dim3(XD / 128, XD / 256, 3), 256, GSMEM>>>(WqTe, WkTe, Mpart, nullptr, KE2);
    msum_hi<<<XD, 256>>>(Mh);

    // 3) prefix sum of x -> hi(Xs) (offsets inline; also zeroes g_r)
    colsum_kernel<<<dim3(XD / 256, CHUNKS), 256>>>(x);
    writeXs_hi<<<dim3(XD / 256, CHUNKS), 256>>>(x);

    // 4) fused P-GEMM + row-dot — single hi*hi pass (error ~2e-4, gate 1e-3)
    gemm_ext<1><<<dim3(XD / 128, NR / 256, 1), 256, GSMEM>>>(Xsh, Mh, r, x, XD);

    // 5) u/w/c0, per-row dots, scalar scan of d
    smallvec_part_kernel<<<dim3(XD / 256, 8), 256>>>(Wq, Wk, bk, bq);
    smallvec_reduce_kernel<<<XD / 256, 256>>>(bq, bk);
    rowdots_kernel<<<NR, 256>>>(x);
    dscan_kernel<<<1, 1024>>>();

    // 6) broadcast
    finalize_kernel<<<NR, 256>>>(out);
}